// round 15
// baseline (speedup 1.0000x reference)
#include <cuda_runtime.h>
#include <stdint.h>

// Problem constants (fixed by the dataset)
#define B_  4
#define L_  5
#define C_  256
#define H_  100
#define W_  252
#define HW_ (H_ * W_)          // 25200
#define HW4_ (HW_ / 4)         // 6300 float4s per channel
#define KSEL 1024
#define NBL (B_ * L_)          // 20
#define NWORDS 788             // ceil(25200/32)
#define NKI 7                  // float4 iterations per thread (7*1024 >= 6300)
#define VPT 6                  // float4s per thread in apply kernels
#define APB (C_ * HW_ / 4 / (256 * VPT))   // 1050 blocks per slice
#define SLICE_ELEMS ((size_t)C_ * HW_)     // 6,451,200 floats per (b,l) slice

// Per-(b,l) pixel bitmask: bit = pixel survives top-K threshold.
__device__ uint32_t g_bitmask[NBL][800];

// Monotone map: float -> uint32 preserving order (ascending).
__device__ __forceinline__ uint32_t f2u(float f) {
    uint32_t u = __float_as_uint(f);
    return (u & 0x80000000u) ? ~u : (u | 0x80000000u);
}

// ---------------------------------------------------------------------------
// SELECT: per (b, l>0), exact K-th-largest radix select over
// d[hw] = max_c (psm[b,l,c,hw] - psm[b,0,c,hw]); writes pixel bitmask.
// Not on the critical path (DRAM saturated by streaming from t=0).
// ---------------------------------------------------------------------------
__global__ __launch_bounds__(1024, 1) void select_kernel(const float* __restrict__ psm) {
    const int blk = blockIdx.x;          // 0..15
    const int b = blk >> 2;
    const int l = 1 + (blk & 3);
    const int bl = b * L_ + l;

    const float4* __restrict__ p_l = reinterpret_cast<const float4*>(psm + (size_t)bl * 2 * HW_);
    const float4* __restrict__ p_0 = reinterpret_cast<const float4*>(psm + (size_t)(b * L_) * 2 * HW_);

    const int tid  = threadIdx.x;
    const int lane = tid & 31;
    const int wid  = tid >> 5;

    // keys[i][j]: pixel hw = (i*1024 + tid)*4 + j. Pad with 0 (minimal mapped
    // value — only inflates bin 0, provably below the K=1024 threshold).
    uint32_t keys[NKI][4];
    #pragma unroll
    for (int i = 0; i < NKI; i++) {
        const int q = i * 1024 + tid;          // float4 index within channel
        if (q < HW4_) {
            float4 a0 = p_l[q];
            float4 a1 = p_l[HW4_ + q];
            float4 b0 = p_0[q];
            float4 b1 = p_0[HW4_ + q];
            keys[i][0] = f2u(fmaxf(a0.x - b0.x, a1.x - b1.x));
            keys[i][1] = f2u(fmaxf(a0.y - b0.y, a1.y - b1.y));
            keys[i][2] = f2u(fmaxf(a0.z - b0.z, a1.z - b1.z));
            keys[i][3] = f2u(fmaxf(a0.w - b0.w, a1.w - b1.w));
        } else {
            keys[i][0] = keys[i][1] = keys[i][2] = keys[i][3] = 0u;
        }
    }

    __shared__ uint32_t hist[2048];
    __shared__ uint32_t suf[2048];
    __shared__ uint32_t segsuf[32];
    __shared__ uint32_t s_prefix, s_rem;
    if (tid == 0) { s_prefix = 0u; s_rem = KSEL; }

    const int shifts[3] = {21, 10, 0};
    #pragma unroll
    for (int p = 0; p < 3; p++) {
        const int shift = shifts[p];
        hist[tid] = 0u; hist[tid + 1024] = 0u;
        __syncthreads();
        const uint32_t prefix = s_prefix;
        const uint32_t rem    = s_rem;

        if (p == 0) {
            // All keys active: warp-aggregated histogram.
            #pragma unroll
            for (int i = 0; i < NKI; i++)
                #pragma unroll
                for (int j = 0; j < 4; j++) {
                    unsigned bin = keys[i][j] >> 21;
                    unsigned peers = __match_any_sync(0xFFFFFFFFu, bin);
                    if (lane == __ffs(peers) - 1)
                        atomicAdd(&hist[bin], __popc(peers));
                }
        } else {
            // Few keys match the prefix: plain predicated atomics.
            const int ps = (p == 1) ? 21 : 10;       // previous pass shift
            #pragma unroll
            for (int i = 0; i < NKI; i++)
                #pragma unroll
                for (int j = 0; j < 4; j++) {
                    uint32_t k = keys[i][j];
                    if ((k >> ps) == (prefix >> ps))
                        atomicAdd(&hist[(k >> shift) & 0x7FFu], 1u);
                }
        }
        __syncthreads();

        // Two-level inclusive suffix scan over 2048 bins.
        const uint32_t h0 = hist[2 * tid];
        const uint32_t h1 = hist[2 * tid + 1];
        uint32_t s = h0 + h1;                         // suffix over pairs in warp
        #pragma unroll
        for (int off = 1; off < 32; off <<= 1) {
            uint32_t t = __shfl_down_sync(0xFFFFFFFFu, s, off);
            if (lane + off < 32) s += t;
        }
        if (lane == 0) segsuf[wid] = s;               // segment total
        __syncthreads();
        if (wid == 0) {                               // suffix over 32 segments
            uint32_t t = segsuf[lane];
            uint32_t s2 = t;
            #pragma unroll
            for (int off = 1; off < 32; off <<= 1) {
                uint32_t u = __shfl_down_sync(0xFFFFFFFFu, s2, off);
                if (lane + off < 32) s2 += u;
            }
            segsuf[lane] = s2 - t;                    // strictly-above total
        }
        __syncthreads();
        const uint32_t above = segsuf[wid];
        suf[2 * tid]     = above + s;                 // incl. suffix of b0
        suf[2 * tid + 1] = above + s - h0;            // incl. suffix of b1
        __syncthreads();

        // Threshold bin: largest d with suf[d] >= rem. Exactly one hit.
        #pragma unroll
        for (int j = 0; j < 2; j++) {
            const int d = 2 * tid + j;
            const uint32_t sd = suf[d];
            if (sd >= rem && (d == 2047 || suf[d + 1] < rem)) {
                const uint32_t hd = j ? h1 : h0;
                s_rem = rem - (sd - hd);
                s_prefix = prefix | ((uint32_t)d << shift);
            }
        }
        __syncthreads();
    }

    const uint32_t T = s_prefix;   // exact key of rank-K element

    // Build bitmask in shared (reuse hist). One atomic per 4 pixels.
    uint32_t* words = hist;
    if (tid < NWORDS) words[tid] = 0u;
    __syncthreads();
    #pragma unroll
    for (int i = 0; i < NKI; i++) {
        const int q = i * 1024 + tid;
        if (q < HW4_) {
            uint32_t nib = (keys[i][0] >= T ? 1u : 0u)
                         | (keys[i][1] >= T ? 2u : 0u)
                         | (keys[i][2] >= T ? 4u : 0u)
                         | (keys[i][3] >= T ? 8u : 0u);
            if (nib) {
                const int hw = q * 4;
                atomicOr(&words[hw >> 5], nib << (hw & 31));
            }
        }
    }
    __syncthreads();
    if (tid < NWORDS) g_bitmask[bl][tid] = words[tid];
}

// ---------------------------------------------------------------------------
// ZERO (ungated): l>0 && mask==0 slices — pure write stream, VPT=6 bursts.
// Early-exits on mask!=0 slices (dep_bits handles those).
// ---------------------------------------------------------------------------
__global__ __launch_bounds__(256) void zero_kernel(const int* __restrict__ mask,
                                                   float* __restrict__ out) {
    const int z = blockIdx.z;                          // 0..15
    const int bl = (z >> 2) * L_ + 1 + (z & 3);        // l in 1..4
    if (mask[bl] != 0) return;

    const size_t slice = (size_t)bl * SLICE_ELEMS;
    const int base4 = (blockIdx.x * 256) * VPT + threadIdx.x;
    float4* __restrict__ o4 = reinterpret_cast<float4*>(out + slice);
    const float4 zv = make_float4(0.f, 0.f, 0.f, 0.f);
    #pragma unroll
    for (int k = 0; k < VPT; k++)
        __stcs(o4 + base4 + k * 256, zv);
}

// ---------------------------------------------------------------------------
// DEP-BITS: l>0 slices with mask!=0. Gated on select via graph edge.
// Bitmask-first: skip the x read when all 4 pixels of a float4 are dead.
// VPT=6 bursts: 6 bit-fetches, then up to 6 loads, then 6 stores — longer
// same-direction runs at the memory controller.
// No device-side fences (R8 lesson: gpu-scope __threadfence = CCTL.IVALL).
// ---------------------------------------------------------------------------
__global__ __launch_bounds__(256) void dep_bits(const float* __restrict__ x,
                                                const int* __restrict__ mask,
                                                float* __restrict__ out) {
    const int z = blockIdx.z;                          // 0..15
    const int bl = (z >> 2) * L_ + 1 + (z & 3);        // l in 1..4
    if (mask[bl] == 0) return;

    const size_t slice = (size_t)bl * SLICE_ELEMS;
    const int base4 = (blockIdx.x * 256) * VPT + threadIdx.x;
    float4* __restrict__ o4 = reinterpret_cast<float4*>(out + slice);
    const float4* __restrict__ x4 = reinterpret_cast<const float4*>(x + slice);
    const float4 zv = make_float4(0.f, 0.f, 0.f, 0.f);

    uint32_t wb[VPT];
    #pragma unroll
    for (int k = 0; k < VPT; k++) {
        const int idx4 = base4 + k * 256;
        const int hw = (idx4 % HW4_) * 4;              // first pixel of float4
        wb[k] = (g_bitmask[bl][hw >> 5] >> (hw & 31)) & 0xFu;
    }

    float4 v[VPT];
    #pragma unroll
    for (int k = 0; k < VPT; k++)
        v[k] = wb[k] ? __ldcs(x4 + base4 + k * 256) : zv;  // predicated loads

    #pragma unroll
    for (int k = 0; k < VPT; k++) {
        float4 r = v[k];
        r.x = (wb[k] & 1u) ? r.x : 0.f;
        r.y = (wb[k] & 2u) ? r.y : 0.f;
        r.z = (wb[k] & 4u) ? r.z : 0.f;
        r.w = (wb[k] & 8u) ? r.w : 0.f;
        __stcs(o4 + base4 + k * 256, r);
    }
}

extern "C" void kernel_launch(void* const* d_in, const int* in_sizes, int n_in,
                              void* d_out, int out_size) {
    const float* x   = (const float*)d_in[0];
    const float* psm = (const float*)d_in[1];
    const int*  mask = (const int*)d_in[2];
    float* out = (float*)d_out;

    // Side streams + events for the fork/join graph. Created once, on the
    // first (non-captured correctness) call; reused during capture.
    static cudaStream_t s_sel = nullptr, s_dep = nullptr, s_cpy = nullptr;
    static cudaEvent_t  e_fork = nullptr, e_join = nullptr, e_dep = nullptr,
                        e_cpy = nullptr;
    if (s_sel == nullptr) {
        cudaStreamCreateWithFlags(&s_sel, cudaStreamNonBlocking);
        cudaStreamCreateWithFlags(&s_dep, cudaStreamNonBlocking);
        cudaStreamCreateWithFlags(&s_cpy, cudaStreamNonBlocking);
        cudaEventCreateWithFlags(&e_fork, cudaEventDisableTiming);
        cudaEventCreateWithFlags(&e_join, cudaEventDisableTiming);
        cudaEventCreateWithFlags(&e_dep,  cudaEventDisableTiming);
        cudaEventCreateWithFlags(&e_cpy,  cudaEventDisableTiming);
    }

    // Graph topology:
    //   main:  e_fork -> zero_kernel -----------------------------\
    //   s_cpy: wait(e_fork) -> 4x memcpy D2D (l==0, copy engine)   \
    //   s_sel: wait(e_fork) -> select -> e_join                     > join
    //   s_dep: wait(e_join) -> dep_bits -> e_dep ------------------/
    cudaEventRecord(e_fork, 0);

    cudaStreamWaitEvent(s_sel, e_fork, 0);
    select_kernel<<<16, 1024, 0, s_sel>>>(psm);
    cudaEventRecord(e_join, s_sel);

    // l==0 slices: bl = 0, 5, 10, 15 — balanced R+W copies on the CE.
    cudaStreamWaitEvent(s_cpy, e_fork, 0);
    for (int b = 0; b < B_; b++) {
        const size_t off = (size_t)(b * L_) * SLICE_ELEMS;
        cudaMemcpyAsync(out + off, x + off, SLICE_ELEMS * sizeof(float),
                        cudaMemcpyDeviceToDevice, s_cpy);
    }
    cudaEventRecord(e_cpy, s_cpy);

    cudaStreamWaitEvent(s_dep, e_join, 0);
    dim3 gd(APB, 1, 16);
    dep_bits<<<gd, 256, 0, s_dep>>>(x, mask, out);     // ~207 MB W + ~58 MB R
    cudaEventRecord(e_dep, s_dep);

    dim3 gz(APB, 1, 16);
    zero_kernel<<<gz, 256>>>(mask, out);               // ~206 MB W, ungated

    cudaStreamWaitEvent(0, e_dep, 0);
    cudaStreamWaitEvent(0, e_cpy, 0);
}

// round 16
// speedup vs baseline: 1.0675x; 1.0675x over previous
#include <cuda_runtime.h>
#include <stdint.h>

// Problem constants (fixed by the dataset)
#define B_  4
#define L_  5
#define C_  256
#define H_  100
#define W_  252
#define HW_ (H_ * W_)          // 25200
#define HW4_ (HW_ / 4)         // 6300 float4s per channel
#define KSEL 1024
#define NBL (B_ * L_)          // 20
#define NWORDS 788             // ceil(25200/32)
#define NK 25                  // scalar keys per thread (padded)
#define VPT 4                  // float4s per thread in apply kernels
#define APB (C_ * HW_ / 4 / (256 * VPT))   // 1575 blocks per slice
#define SLICE_ELEMS ((size_t)C_ * HW_)     // 6,451,200 floats per (b,l) slice

// Per-(b,l) pixel bitmask: bit = pixel survives top-K threshold.
__device__ uint32_t g_bitmask[NBL][800];

// Monotone map: float -> uint32 preserving order (ascending).
__device__ __forceinline__ uint32_t f2u(float f) {
    uint32_t u = __float_as_uint(f);
    return (u & 0x80000000u) ? ~u : (u | 0x80000000u);
}

// ---------------------------------------------------------------------------
// SELECT: per (b, l>0), exact K-th-largest radix select over
// d[hw] = max_c (psm[b,l,c,hw] - psm[b,0,c,hw]); writes pixel bitmask.
// Scalar-load variant (measured 25.7us vs 31.7us for float4 loads — earlier
// gate release lets dep_bits' reads join the write-heavy phase sooner).
// 3 radix passes (11+11+10 bits), 2048-bin histogram, shuffle suffix-scan.
// ---------------------------------------------------------------------------
__global__ __launch_bounds__(1024, 1) void select_kernel(const float* __restrict__ psm) {
    const int blk = blockIdx.x;          // 0..15
    const int b = blk >> 2;
    const int l = 1 + (blk & 3);
    const int bl = b * L_ + l;

    const float* __restrict__ p_l = psm + (size_t)bl * 2 * HW_;
    const float* __restrict__ p_0 = psm + (size_t)(b * L_) * 2 * HW_;

    const int tid  = threadIdx.x;
    const int lane = tid & 31;
    const int wid  = tid >> 5;

    // Uniform NK keys per thread; pad with 0 (minimal mapped value — only
    // inflates bin 0, provably below the K=1024 threshold region).
    uint32_t keys[NK];
    #pragma unroll
    for (int i = 0; i < NK; i++) {
        int hw = tid + i * 1024;
        if (hw < HW_) {
            float d0 = p_l[hw]       - p_0[hw];
            float d1 = p_l[HW_ + hw] - p_0[HW_ + hw];
            keys[i] = f2u(fmaxf(d0, d1));
        } else {
            keys[i] = 0u;
        }
    }

    __shared__ uint32_t hist[2048];
    __shared__ uint32_t suf[2048];
    __shared__ uint32_t segsuf[32];
    __shared__ uint32_t s_prefix, s_rem;
    if (tid == 0) { s_prefix = 0u; s_rem = KSEL; }

    const int shifts[3] = {21, 10, 0};
    #pragma unroll
    for (int p = 0; p < 3; p++) {
        const int shift = shifts[p];
        hist[tid] = 0u; hist[tid + 1024] = 0u;
        __syncthreads();
        const uint32_t prefix = s_prefix;
        const uint32_t rem    = s_rem;

        if (p == 0) {
            // All keys active: warp-aggregated histogram.
            #pragma unroll
            for (int i = 0; i < NK; i++) {
                unsigned bin = keys[i] >> 21;
                unsigned peers = __match_any_sync(0xFFFFFFFFu, bin);
                if (lane == __ffs(peers) - 1)
                    atomicAdd(&hist[bin], __popc(peers));
            }
        } else {
            // Few keys match the prefix: plain predicated atomics.
            const int ps = (p == 1) ? 21 : 10;       // previous pass shift
            #pragma unroll
            for (int i = 0; i < NK; i++) {
                uint32_t k = keys[i];
                if ((k >> ps) == (prefix >> ps))
                    atomicAdd(&hist[(k >> shift) & 0x7FFu], 1u);
            }
        }
        __syncthreads();

        // Two-level inclusive suffix scan over 2048 bins.
        const uint32_t h0 = hist[2 * tid];
        const uint32_t h1 = hist[2 * tid + 1];
        uint32_t s = h0 + h1;                         // suffix over pairs in warp
        #pragma unroll
        for (int off = 1; off < 32; off <<= 1) {
            uint32_t t = __shfl_down_sync(0xFFFFFFFFu, s, off);
            if (lane + off < 32) s += t;
        }
        if (lane == 0) segsuf[wid] = s;               // segment total
        __syncthreads();
        if (wid == 0) {                               // suffix over 32 segments
            uint32_t t = segsuf[lane];
            uint32_t s2 = t;
            #pragma unroll
            for (int off = 1; off < 32; off <<= 1) {
                uint32_t u = __shfl_down_sync(0xFFFFFFFFu, s2, off);
                if (lane + off < 32) s2 += u;
            }
            segsuf[lane] = s2 - t;                    // strictly-above total
        }
        __syncthreads();
        const uint32_t above = segsuf[wid];
        suf[2 * tid]     = above + s;                 // incl. suffix of b0
        suf[2 * tid + 1] = above + s - h0;            // incl. suffix of b1
        __syncthreads();

        // Threshold bin: largest d with suf[d] >= rem. Exactly one hit.
        #pragma unroll
        for (int j = 0; j < 2; j++) {
            const int d = 2 * tid + j;
            const uint32_t sd = suf[d];
            if (sd >= rem && (d == 2047 || suf[d + 1] < rem)) {
                const uint32_t hd = j ? h1 : h0;
                s_rem = rem - (sd - hd);
                s_prefix = prefix | ((uint32_t)d << shift);
            }
        }
        __syncthreads();
    }

    const uint32_t T = s_prefix;   // exact key of rank-K element

    // Build bitmask in shared (reuse hist), then flush to global.
    uint32_t* words = hist;
    if (tid < NWORDS) words[tid] = 0u;
    __syncthreads();
    #pragma unroll
    for (int i = 0; i < NK; i++) {
        int hw = tid + i * 1024;
        if (hw < HW_ && keys[i] >= T)
            atomicOr(&words[hw >> 5], 1u << (hw & 31));
    }
    __syncthreads();
    if (tid < NWORDS) g_bitmask[bl][tid] = words[tid];
}

// ---------------------------------------------------------------------------
// STREAM (ungated): all slices needing no bitmask. SM streaming only (R15
// lesson: the copy engine cannot match SM local-D2D bandwidth).
//   l==0           : copy x -> out
//   l>0 && mask==0 : zero-fill (NO x read)
//   l>0 && mask!=0 : skip (dep_bits handles)
// grid = (1575, 1, 20), block = 256, MLP=4, streaming hints.
// ---------------------------------------------------------------------------
__global__ __launch_bounds__(256) void stream_kernel(const float* __restrict__ x,
                                                     const int* __restrict__ mask,
                                                     float* __restrict__ out) {
    const int bl = blockIdx.z;                         // 0..19
    const int l = bl % L_;
    const size_t slice = (size_t)bl * SLICE_ELEMS;
    const int base4 = (blockIdx.x * 256) * VPT + threadIdx.x;
    float4* __restrict__ o4 = reinterpret_cast<float4*>(out + slice);

    if (l == 0) {
        const float4* __restrict__ x4 = reinterpret_cast<const float4*>(x + slice);
        float4 v[VPT];
        #pragma unroll
        for (int k = 0; k < VPT; k++)
            v[k] = __ldcs(x4 + base4 + k * 256);
        #pragma unroll
        for (int k = 0; k < VPT; k++)
            __stcs(o4 + base4 + k * 256, v[k]);
        return;
    }
    if (mask[bl] != 0) return;                         // dep_bits' slice

    const float4 zv = make_float4(0.f, 0.f, 0.f, 0.f);
    #pragma unroll
    for (int k = 0; k < VPT; k++)
        __stcs(o4 + base4 + k * 256, zv);
}

// ---------------------------------------------------------------------------
// DEP-BITS: l>0 slices with mask!=0. Gated on select via graph edge.
// Bitmask-first: skip the x read when all 4 pixels of a float4 are dead
// (~96% dead -> ~72% of read sectors skipped).
// No device-side fences (R8 lesson: gpu-scope __threadfence = CCTL.IVALL).
// ---------------------------------------------------------------------------
__global__ __launch_bounds__(256) void dep_bits(const float* __restrict__ x,
                                                const int* __restrict__ mask,
                                                float* __restrict__ out) {
    const int z = blockIdx.z;                          // 0..15
    const int bl = (z >> 2) * L_ + 1 + (z & 3);        // l in 1..4
    if (mask[bl] == 0) return;

    const size_t slice = (size_t)bl * SLICE_ELEMS;
    const int base4 = (blockIdx.x * 256) * VPT + threadIdx.x;
    float4* __restrict__ o4 = reinterpret_cast<float4*>(out + slice);
    const float4* __restrict__ x4 = reinterpret_cast<const float4*>(x + slice);
    const float4 zv = make_float4(0.f, 0.f, 0.f, 0.f);

    uint32_t wb[VPT];
    #pragma unroll
    for (int k = 0; k < VPT; k++) {
        const int idx4 = base4 + k * 256;
        const int hw = (idx4 % HW4_) * 4;              // first pixel of float4
        wb[k] = (g_bitmask[bl][hw >> 5] >> (hw & 31)) & 0xFu;
    }

    float4 v[VPT];
    #pragma unroll
    for (int k = 0; k < VPT; k++)
        v[k] = wb[k] ? __ldcs(x4 + base4 + k * 256) : zv;  // predicated loads

    #pragma unroll
    for (int k = 0; k < VPT; k++) {
        float4 r = v[k];
        r.x = (wb[k] & 1u) ? r.x : 0.f;
        r.y = (wb[k] & 2u) ? r.y : 0.f;
        r.z = (wb[k] & 4u) ? r.z : 0.f;
        r.w = (wb[k] & 8u) ? r.w : 0.f;
        __stcs(o4 + base4 + k * 256, r);
    }
}

extern "C" void kernel_launch(void* const* d_in, const int* in_sizes, int n_in,
                              void* d_out, int out_size) {
    const float* x   = (const float*)d_in[0];
    const float* psm = (const float*)d_in[1];
    const int*  mask = (const int*)d_in[2];
    float* out = (float*)d_out;

    // Side streams + events for the fork/join graph. Created once, on the
    // first (non-captured correctness) call; reused during capture.
    static cudaStream_t s_sel = nullptr, s_dep = nullptr;
    static cudaEvent_t  e_fork = nullptr, e_join = nullptr, e_dep = nullptr;
    if (s_sel == nullptr) {
        cudaStreamCreateWithFlags(&s_sel, cudaStreamNonBlocking);
        cudaStreamCreateWithFlags(&s_dep, cudaStreamNonBlocking);
        cudaEventCreateWithFlags(&e_fork, cudaEventDisableTiming);
        cudaEventCreateWithFlags(&e_join, cudaEventDisableTiming);
        cudaEventCreateWithFlags(&e_dep,  cudaEventDisableTiming);
    }

    // Graph topology:
    //   main:  e_fork -> stream_kernel ----------------------\
    //   s_sel: wait(e_fork) -> select -> e_join               > join -> done
    //   s_dep: wait(e_join) -> dep_bits -> e_dep ------------/
    cudaEventRecord(e_fork, 0);
    cudaStreamWaitEvent(s_sel, e_fork, 0);
    select_kernel<<<16, 1024, 0, s_sel>>>(psm);
    cudaEventRecord(e_join, s_sel);

    cudaStreamWaitEvent(s_dep, e_join, 0);
    dim3 gd(APB, 1, 16);
    dep_bits<<<gd, 256, 0, s_dep>>>(x, mask, out);     // ~207 MB W + ~58 MB R
    cudaEventRecord(e_dep, s_dep);

    dim3 gs(APB, 1, NBL);
    stream_kernel<<<gs, 256>>>(x, mask, out);          // ~412 MB, ungated

    cudaStreamWaitEvent(0, e_dep, 0);
}